// round 9
// baseline (speedup 1.0000x reference)
#include <cuda_runtime.h>
#include <math.h>
#include <float.h>

#define TPB    1024
#define KNN_K  16
#define NBUCK  64
#define FULLM  0xFFFFFFFFu
#define XMIN   (-4.8f)
#define XMAX   ( 4.8f)
#define BW     ((XMAX - XMIN) / (float)NBUCK)
#define INVBW  ((float)NBUCK / (XMAX - XMIN))
#define SAFE   1e-5f

// scratch (static device arrays; allocation-free rule)
__device__ int                g_idx [65536 * KNN_K];
__device__ float              g_w   [65536 * KNN_K];
__device__ float              g_Dfwd[65536];
__device__ unsigned long long g_Drev[65536];

// bucket-build scratch
__device__ int            g_hist[16 * NBUCK];        // zero-init; re-zeroed by k_scan
__device__ int            g_off [16 * (NBUCK + 1)];
__device__ int            g_cur [16 * NBUCK];
__device__ float4         g_rc  [65536];             // reordered (x,y,z,|p|^2)
__device__ unsigned short g_rid [65536];             // orig index per position

__device__ __forceinline__ int bucket_of_x(float x) {
    int ib = (int)((x - XMIN) * INVBW);
    return min(max(ib, 0), NBUCK - 1);
}

// ---------- pure zero-fill + diagonal (homogeneous store kernel) ----------
// N is a power of two here (4096): bit tricks for row/col from flat f4 index.
__global__ void __launch_bounds__(TPB)
k_fill(float4* __restrict__ out4, int n4, long long total4)
{
    const float4 z4 = make_float4(0.0f, 0.0f, 0.0f, 0.0f);
    const int sN = 31 - __clz(n4);              // log2(N/4)
    const int rowmask = 4 * n4 - 1;             // N-1
    const int colmask = n4 - 1;
    long long f = (long long)blockIdx.x * TPB + threadIdx.x;
    const long long stride = (long long)gridDim.x * TPB;
    for (; f < total4; f += stride) {
        __stcs(&out4[f], z4);
        int row  = (int)((f >> sN)) & rowmask;  // row within its NxN matrix
        int col4 = (int)f & colmask;
        if (col4 == (row >> 2)) {               // this f4 holds the diagonal
            float4 v = z4;
            int c = row & 3;
            v.x = (c == 0) ? 1.0f : 0.0f;
            v.y = (c == 1) ? 1.0f : 0.0f;
            v.z = (c == 2) ? 1.0f : 0.0f;
            v.w = (c == 3) ? 1.0f : 0.0f;
            __stcs(&out4[f], v);                // same thread, same addr: ordered
        }
    }
}

// ---------- prepass ----------
__global__ void k_hist(const float* __restrict__ xyz, int N, int B)
{
    int t = blockIdx.x * blockDim.x + threadIdx.x;
    if (t >= B * N) return;
    g_Drev[t] = 0ull;                       // pre-zero for epilogue atomics
    int b = t / N, n = t - b * N;
    float x = xyz[(size_t)b * 3 * N + n];
    atomicAdd(&g_hist[b * NBUCK + bucket_of_x(x)], 1);
}

__global__ void k_scan(int B)
{
    int warp = threadIdx.x >> 5, lane = threadIdx.x & 31;
    if (warp >= B) return;
    int base = warp * NBUCK;
    int v0 = g_hist[base + lane];
    int v1 = g_hist[base + 32 + lane];
    int s0 = v0, s1 = v1;
    for (int d = 1; d < 32; d <<= 1) {
        int t0 = __shfl_up_sync(FULLM, s0, d);
        int t1 = __shfl_up_sync(FULLM, s1, d);
        if (lane >= d) { s0 += t0; s1 += t1; }
    }
    s1 += __shfl_sync(FULLM, s0, 31);
    int ob = warp * (NBUCK + 1);
    if (lane == 0) g_off[ob] = 0;
    g_off[ob + 1 + lane]  = s0;
    g_off[ob + 33 + lane] = s1;
    g_cur[base + lane]      = s0 - v0;
    g_cur[base + 32 + lane] = s1 - v1;
    g_hist[base + lane] = 0;                 // ready for next graph replay
    g_hist[base + 32 + lane] = 0;
}

__global__ void k_reorder(const float* __restrict__ xyz, int N, int B)
{
    int t = blockIdx.x * blockDim.x + threadIdx.x;
    if (t >= B * N) return;
    int b = t / N, n = t - b * N;
    const float* X = xyz + (size_t)b * 3 * N;
    float x = X[n], y = X[N + n], z = X[2 * N + n];
    float sq = fmaf(x, x, fmaf(y, y, z * z));
    int pos = atomicAdd(&g_cur[b * NBUCK + bucket_of_x(x)], 1);
    g_rc [b * N + pos] = make_float4(x, y, z, sq);
    g_rid[b * N + pos] = (unsigned short)n;
}

// ---------- KNN only (homogeneous compute kernel, 64 queries/block) ----------
__global__ void __launch_bounds__(TPB, 2)
k_knn(int N, int B)
{
    extern __shared__ char smraw[];
    const int tid = threadIdx.x;
    const int bid = blockIdx.x;

    float4*         rc  = reinterpret_cast<float4*>(smraw);            // N float4
    unsigned short* rid = reinterpret_cast<unsigned short*>(rc + N);   // N ushort
    int*            off = reinterpret_cast<int*>(rid + N);             // NBUCK+1

    const int qpb = (TPB / 32) * 2;             // 64 queries per block
    const int blocks_per_b = N / qpb;
    const int b = bid / blocks_per_b;
    const int qbase = (bid - b * blocks_per_b) * qpb;
    const int bN = b * N;

    for (int n = tid; n < N; n += TPB) rc[n]  = g_rc[bN + n];
    for (int n = tid; n < N; n += TPB) rid[n] = g_rid[bN + n];
    if (tid <= NBUCK) off[tid] = g_off[b * (NBUCK + 1) + tid];
    __syncthreads();

    const int warp = tid >> 5, lane = tid & 31;
    const int g = lane >> 4, sub = lane & 15;
    const int pos0 = qbase + warp * 2;          // bucket-sorted positions

    // queries kept ONLY in pre-scaled form to save registers: a = -2q, qw=|q|^2
    float a0x, a0y, a0z, q0w, a1x, a1y, a1z, q1w;
    {
        float4 q0 = rc[pos0];
        float4 q1 = rc[pos0 + 1];
        a0x = -2.0f * q0.x; a0y = -2.0f * q0.y; a0z = -2.0f * q0.z; q0w = q0.w;
        a1x = -2.0f * q1.x; a1y = -2.0f * q1.y; a1z = -2.0f * q1.z; q1w = q1.w;
    }

    // sorted-across-lanes top-16 in e-space; li = POSITION in rc
    float ld = FLT_MAX; int li = 0;
    float wt0 = FLT_MAX, wt1 = FLT_MAX;

    auto process = [&](int start, int end) {
        for (int p = start; p < end; p += 32) {
            int pp = p + lane;
            bool valid = pp < end;
            float4 c = rc[valid ? pp : end - 1];
            float e0 = fmaf(a0x, c.x, fmaf(a0y, c.y, fmaf(a0z, c.z, c.w)));
            float e1 = fmaf(a1x, c.x, fmaf(a1y, c.y, fmaf(a1z, c.z, c.w)));
            unsigned bal0 = __ballot_sync(FULLM, valid && (e0 < wt0));
            unsigned bal1 = __ballot_sync(FULLM, valid && (e1 < wt1));
            if ((bal0 | bal1) == 0u) continue;
            do {
                int s0 = __ffs(bal0) - 1;
                int s1 = __ffs(bal1) - 1;
                float dd0 = __shfl_sync(FULLM, e0, s0 & 31);
                float dd1 = __shfl_sync(FULLM, e1, s1 & 31);
                bool have = g ? (bal1 != 0u) : (bal0 != 0u);
                float dd = g ? dd1 : dd0;
                int   jj = p + ((g ? s1 : s0) & 31);
                bool pr = have && (dd < ld);
                unsigned pb = __ballot_sync(FULLM, pr);
                float sld = __shfl_up_sync(FULLM, ld, 1);
                int   sli = __shfl_up_sync(FULLM, li, 1);
                bool prevpr = (sub > 0) && ((pb >> (lane - 1)) & 1u);
                if (pr) { ld = prevpr ? sld : dd; li = prevpr ? sli : jj; }
                bal0 &= bal0 - 1;
                bal1 &= bal1 - 1;
            } while (bal0 | bal1);
            wt0 = __shfl_sync(FULLM, ld, 15);
            wt1 = __shfl_sync(FULLM, ld, 31);
        }
    };

    // buckets of the two queries (binary search over off[], warp-uniform)
    int blo, bhi;
    {
        int lo = 0, hi = NBUCK - 1;
        while (lo < hi) { int mid = (lo + hi + 1) >> 1; if (off[mid] <= pos0) lo = mid; else hi = mid - 1; }
        blo = lo;
        lo = blo; hi = NBUCK - 1;
        int p1 = pos0 + 1;
        while (lo < hi) { int mid = (lo + hi + 1) >> 1; if (off[mid] <= p1) lo = mid; else hi = mid - 1; }
        bhi = lo;
    }

    process(off[blo], off[bhi + 1]);

    bool leftOpen = blo > 0, rightOpen = bhi < NBUCK - 1;
    while (leftOpen || rightOpen) {
        float qx0 = -0.5f * a0x, qx1 = -0.5f * a1x;
        float r20 = (wt0 + q0w) * 1.0001f + 1e-6f;    // d^2 bound, slack for fp
        float r21 = (wt1 + q1w) * 1.0001f + 1e-6f;
        float LBx = XMIN + blo * BW;
        float RBx = XMIN + (bhi + 1) * BW;
        if (leftOpen) {
            float gl0 = fmaxf(qx0 - LBx - SAFE, 0.0f);
            float gl1 = fmaxf(qx1 - LBx - SAFE, 0.0f);
            if (gl0 * gl0 >= r20 && gl1 * gl1 >= r21) leftOpen = false;
        }
        if (rightOpen) {
            float gr0 = fmaxf(RBx - qx0 - SAFE, 0.0f);
            float gr1 = fmaxf(RBx - qx1 - SAFE, 0.0f);
            if (gr0 * gr0 >= r20 && gr1 * gr1 >= r21) rightOpen = false;
        }
        if (!(leftOpen || rightOpen)) break;
        bool goLeft = (leftOpen && rightOpen) ? ((qx0 - LBx) < (RBx - qx1)) : leftOpen;
        if (goLeft) {
            blo--;
            process(off[blo], off[blo + 1]);
            leftOpen = blo > 0;
        } else {
            bhi++;
            process(off[bhi], off[bhi + 1]);
            rightOpen = bhi < NBUCK - 1;
        }
    }

    // epilogue: exact weight recomputation from coordinates (faithful to ref)
    float qx = -0.5f * (g ? a1x : a0x);
    float qy = -0.5f * (g ? a1y : a0y);
    float qz = -0.5f * (g ? a1z : a0z);
    const float4 nbp = rc[li];
    float dx = qx - nbp.x, dy = qy - nbp.y, dz = qz - nbp.z;
    float dist2 = fmaf(dx, dx, fmaf(dy, dy, dz * dz));
    float w = expf(-0.5f * dist2);

    const int qorig = rid[pos0 + g];
    const int qglob = bN + qorig;
    const int norig = rid[li];
    g_idx[qglob * KNN_K + sub] = norig;
    g_w [qglob * KNN_K + sub] = w;

    // reverse-degree scatter folded in (fixed-point => deterministic)
    unsigned long long inc = (unsigned long long)((double)w * 4294967296.0);
    atomicAdd(&g_Drev[bN + norig], inc);

    float s = w;
    s += __shfl_xor_sync(FULLM, s, 8);
    s += __shfl_xor_sync(FULLM, s, 4);
    s += __shfl_xor_sync(FULLM, s, 2);
    s += __shfl_xor_sync(FULLM, s, 1);
    if (sub == 0) g_Dfwd[qglob] = 0.5f * s;
}

// Sparse Laplacian scatter.
__global__ void k_lap(float* __restrict__ out, int N, int total_edges)
{
    int e = blockIdx.x * blockDim.x + threadIdx.x;
    if (e >= total_edges) return;
    int q = e >> 4;
    int b = q / N;
    int i = q - b * N;
    int j = g_idx[e];
    float w = g_w[e];

    float Di = g_Dfwd[q]         + (float)((double)g_Drev[q]         * (0.5 / 4294967296.0));
    float Dj = g_Dfwd[b * N + j] + (float)((double)g_Drev[b * N + j] * (0.5 / 4294967296.0));
    float di = 1.0f / sqrtf(fmaxf(Di, 1e-6f));
    float dj = 1.0f / sqrtf(fmaxf(Dj, 1e-6f));
    float v = -((0.5f * w) * di) * dj;

    float* Lb = out + (size_t)b * N * (size_t)N;
    atomicAdd(Lb + (size_t)i * N + j, v);
    atomicAdd(Lb + (size_t)j * N + i, v);
}

extern "C" void kernel_launch(void* const* d_in, const int* in_sizes, int n_in,
                              void* d_out, int out_size)
{
    const float* xyz = (const float*)d_in[0];
    float* out = (float*)d_out;

    long long inel = in_sizes[0];                       // B*3*N
    int N = (int)((3LL * (long long)out_size) / inel);  // (3*B*N^2)/(3*B*N)
    int B = (int)(inel / (3LL * (long long)N));

    // 1) zero-fill + diagonal first: its L2->DRAM writeback drains under the
    //    following kernels (kernel completion does not wait for writeback).
    long long total4 = (long long)B * N * (N / 4);
    k_fill<<<2048, TPB>>>((float4*)out, N / 4, total4);

    // 2) prepass
    int pts = B * N;
    int pb = (pts + 255) / 256;
    k_hist<<<pb, 256>>>(xyz, N, B);
    k_scan<<<1, 32 * B>>>(B);
    k_reorder<<<pb, 256>>>(xyz, N, B);

    // 3) KNN (homogeneous, 256 blocks, all wave-1)
    int nb_knn = B * (N / 64);
    size_t smem = (size_t)N * sizeof(float4) + (size_t)N * sizeof(unsigned short)
                + (size_t)(NBUCK + 1) * sizeof(int);
    cudaFuncSetAttribute(k_knn, cudaFuncAttributeMaxDynamicSharedMemorySize, (int)smem);
    k_knn<<<nb_knn, TPB, smem>>>(N, B);

    // 4) Laplacian scatter
    int edges = B * N * KNN_K;
    int eb = (edges + 255) / 256;
    k_lap<<<eb, 256>>>(out, N, edges);
}

// round 10
// speedup vs baseline: 1.1826x; 1.1826x over previous
#include <cuda_runtime.h>
#include <math.h>
#include <float.h>

#define TPB    1024
#define KNN_K  16
#define NBUCK  64
#define FULLM  0xFFFFFFFFu
#define XMIN   (-4.8f)
#define XMAX   ( 4.8f)
#define BW     ((XMAX - XMIN) / (float)NBUCK)
#define INVBW  ((float)NBUCK / (XMAX - XMIN))
#define SAFE   1e-5f

// scratch (static device arrays; allocation-free rule)
__device__ int                g_idx [65536 * KNN_K];
__device__ float              g_w   [65536 * KNN_K];
__device__ float              g_Dfwd[65536];
__device__ unsigned long long g_Drev[65536];

__device__ int            g_off [16 * (NBUCK + 1)];
__device__ float4         g_rc  [65536];             // reordered (x,y,z,|p|^2)
__device__ unsigned short g_rid [65536];             // orig index per position

__device__ __forceinline__ int bucket_of_x(float x) {
    int ib = (int)((x - XMIN) * INVBW);
    return min(max(ib, 0), NBUCK - 1);
}

// ---------- single-kernel prepass: hist + scan + reorder + Drev zero ----------
// grid = B blocks (one batch each), 1024 threads.
__global__ void __launch_bounds__(1024)
k_bucket(const float* __restrict__ xyz, int N, int B)
{
    __shared__ int h[NBUCK];
    __shared__ int cur[NBUCK];
    const int b = blockIdx.x;
    const int tid = threadIdx.x;
    const int bN = b * N;
    const float* X = xyz + (size_t)b * 3 * N;

    if (tid < NBUCK) h[tid] = 0;
    __syncthreads();

    for (int n = tid; n < N; n += 1024) {
        g_Drev[bN + n] = 0ull;              // pre-zero for knn epilogue atomics
        atomicAdd(&h[bucket_of_x(X[n])], 1);
    }
    __syncthreads();

    // warp 0: inclusive scan of 64 counts, publish offsets
    if (tid < 32) {
        int v0 = h[tid], v1 = h[tid + 32];
        int s0 = v0, s1 = v1;
        for (int d = 1; d < 32; d <<= 1) {
            int t0 = __shfl_up_sync(FULLM, s0, d);
            int t1 = __shfl_up_sync(FULLM, s1, d);
            if (tid >= d) { s0 += t0; s1 += t1; }
        }
        s1 += __shfl_sync(FULLM, s0, 31);
        int ob = b * (NBUCK + 1);
        if (tid == 0) g_off[ob] = 0;
        g_off[ob + 1 + tid]  = s0;
        g_off[ob + 33 + tid] = s1;
        cur[tid]      = s0 - v0;            // exclusive offsets as counters
        cur[tid + 32] = s1 - v1;
    }
    __syncthreads();

    for (int n = tid; n < N; n += 1024) {
        float x = X[n], y = X[N + n], z = X[2 * N + n];
        float sq = fmaf(x, x, fmaf(y, y, z * z));
        int pos = atomicAdd(&cur[bucket_of_x(x)], 1);
        g_rc [bN + pos] = make_float4(x, y, z, sq);
        g_rid[bN + pos] = (unsigned short)n;
    }
}

// ---------- fused KNN + dense init (round-8 structure, unchanged) ----------
// Blocks [0, nb_knn): KNN, 64 queries each (2/warp), all in wave 1.
// Blocks [nb_knn, ...): grid-stride zero-fill rows (lean streaming stores,
// diagonal patched afterwards by the owning thread).
__global__ void __launch_bounds__(TPB, 2)
k_knn_init(float* __restrict__ out, int N, int B, int nb_knn, int nb_ms)
{
    extern __shared__ char smraw[];
    const int tid = threadIdx.x;
    const int bid = blockIdx.x;

    if (bid >= nb_knn) {
        // ------------- zero-fill + diagonal (lean inner loop) -------------
        const float4 z4 = make_float4(0.0f, 0.0f, 0.0f, 0.0f);
        int msid  = bid - nb_knn;
        int nrows = B * N;
        int n4 = N >> 2;
        for (int r = msid; r < nrows; r += nb_ms) {
            int b = r / N;
            int i = r - b * N;
            float4* row = reinterpret_cast<float4*>(out + ((size_t)b * N + i) * (size_t)N);
            #pragma unroll 2
            for (int f = tid; f < n4; f += TPB)
                __stcs(row + f, z4);
            // diagonal patch: same thread that zeroed float4 (i>>2) rewrites it
            int fd = i >> 2;
            if (tid == (fd & (TPB - 1))) {
                float4 v = z4;
                ((float*)&v)[i & 3] = 1.0f;
                __stcs(row + fd, v);
            }
        }
        return;
    }

    // ---------------- KNN path (smem-cached, 1-D buckets) ---------
    float4*         rc  = reinterpret_cast<float4*>(smraw);            // N float4
    unsigned short* rid = reinterpret_cast<unsigned short*>(rc + N);   // N ushort
    int*            off = reinterpret_cast<int*>(rid + N);             // NBUCK+1

    const int qpb = (TPB / 32) * 2;             // 64 queries per block
    const int blocks_per_b = N / qpb;
    const int b = bid / blocks_per_b;
    const int qbase = (bid - b * blocks_per_b) * qpb;
    const int bN = b * N;

    for (int n = tid; n < N; n += TPB) rc[n]  = g_rc[bN + n];
    for (int n = tid; n < N; n += TPB) rid[n] = g_rid[bN + n];
    if (tid <= NBUCK) off[tid] = g_off[b * (NBUCK + 1) + tid];
    __syncthreads();

    const int warp = tid >> 5, lane = tid & 31;
    const int g = lane >> 4, sub = lane & 15;
    const int pos0 = qbase + warp * 2;          // bucket-sorted positions

    // queries kept ONLY in pre-scaled form to save registers: a = -2q, qw=|q|^2
    float a0x, a0y, a0z, q0w, a1x, a1y, a1z, q1w;
    {
        float4 q0 = rc[pos0];
        float4 q1 = rc[pos0 + 1];
        a0x = -2.0f * q0.x; a0y = -2.0f * q0.y; a0z = -2.0f * q0.z; q0w = q0.w;
        a1x = -2.0f * q1.x; a1y = -2.0f * q1.y; a1z = -2.0f * q1.z; q1w = q1.w;
    }

    // sorted-across-lanes top-16 in e-space; li = POSITION in rc
    float ld = FLT_MAX; int li = 0;
    float wt0 = FLT_MAX, wt1 = FLT_MAX;

    auto process = [&](int start, int end) {
        for (int p = start; p < end; p += 32) {
            int pp = p + lane;
            bool valid = pp < end;
            float4 c = rc[valid ? pp : end - 1];
            float e0 = fmaf(a0x, c.x, fmaf(a0y, c.y, fmaf(a0z, c.z, c.w)));
            float e1 = fmaf(a1x, c.x, fmaf(a1y, c.y, fmaf(a1z, c.z, c.w)));
            unsigned bal0 = __ballot_sync(FULLM, valid && (e0 < wt0));
            unsigned bal1 = __ballot_sync(FULLM, valid && (e1 < wt1));
            if ((bal0 | bal1) == 0u) continue;
            do {
                int s0 = __ffs(bal0) - 1;
                int s1 = __ffs(bal1) - 1;
                float dd0 = __shfl_sync(FULLM, e0, s0 & 31);
                float dd1 = __shfl_sync(FULLM, e1, s1 & 31);
                bool have = g ? (bal1 != 0u) : (bal0 != 0u);
                float dd = g ? dd1 : dd0;
                int   jj = p + ((g ? s1 : s0) & 31);
                bool pr = have && (dd < ld);
                unsigned pb = __ballot_sync(FULLM, pr);
                float sld = __shfl_up_sync(FULLM, ld, 1);
                int   sli = __shfl_up_sync(FULLM, li, 1);
                bool prevpr = (sub > 0) && ((pb >> (lane - 1)) & 1u);
                if (pr) { ld = prevpr ? sld : dd; li = prevpr ? sli : jj; }
                bal0 &= bal0 - 1;
                bal1 &= bal1 - 1;
            } while (bal0 | bal1);
            wt0 = __shfl_sync(FULLM, ld, 15);
            wt1 = __shfl_sync(FULLM, ld, 31);
        }
    };

    // buckets of the two queries (binary search over off[], warp-uniform)
    int blo, bhi;
    {
        int lo = 0, hi = NBUCK - 1;
        while (lo < hi) { int mid = (lo + hi + 1) >> 1; if (off[mid] <= pos0) lo = mid; else hi = mid - 1; }
        blo = lo;
        lo = blo; hi = NBUCK - 1;
        int p1 = pos0 + 1;
        while (lo < hi) { int mid = (lo + hi + 1) >> 1; if (off[mid] <= p1) lo = mid; else hi = mid - 1; }
        bhi = lo;
    }

    process(off[blo], off[bhi + 1]);

    bool leftOpen = blo > 0, rightOpen = bhi < NBUCK - 1;
    while (leftOpen || rightOpen) {
        float qx0 = -0.5f * a0x, qx1 = -0.5f * a1x;
        float r20 = (wt0 + q0w) * 1.0001f + 1e-6f;    // d^2 bound, slack for fp
        float r21 = (wt1 + q1w) * 1.0001f + 1e-6f;
        float LBx = XMIN + blo * BW;
        float RBx = XMIN + (bhi + 1) * BW;
        if (leftOpen) {
            float gl0 = fmaxf(qx0 - LBx - SAFE, 0.0f);
            float gl1 = fmaxf(qx1 - LBx - SAFE, 0.0f);
            if (gl0 * gl0 >= r20 && gl1 * gl1 >= r21) leftOpen = false;
        }
        if (rightOpen) {
            float gr0 = fmaxf(RBx - qx0 - SAFE, 0.0f);
            float gr1 = fmaxf(RBx - qx1 - SAFE, 0.0f);
            if (gr0 * gr0 >= r20 && gr1 * gr1 >= r21) rightOpen = false;
        }
        if (!(leftOpen || rightOpen)) break;
        bool goLeft = (leftOpen && rightOpen) ? ((qx0 - LBx) < (RBx - qx1)) : leftOpen;
        if (goLeft) {
            blo--;
            process(off[blo], off[blo + 1]);
            leftOpen = blo > 0;
        } else {
            bhi++;
            process(off[bhi], off[bhi + 1]);
            rightOpen = bhi < NBUCK - 1;
        }
    }

    // epilogue: exact weight recomputation from coordinates (faithful to ref)
    float qx = -0.5f * (g ? a1x : a0x);
    float qy = -0.5f * (g ? a1y : a0y);
    float qz = -0.5f * (g ? a1z : a0z);
    const float4 nbp = rc[li];
    float dx = qx - nbp.x, dy = qy - nbp.y, dz = qz - nbp.z;
    float dist2 = fmaf(dx, dx, fmaf(dy, dy, dz * dz));
    float w = expf(-0.5f * dist2);

    const int qorig = rid[pos0 + g];
    const int qglob = bN + qorig;
    const int norig = rid[li];
    g_idx[qglob * KNN_K + sub] = norig;
    g_w [qglob * KNN_K + sub] = w;

    // reverse-degree scatter folded in (fixed-point => deterministic)
    unsigned long long inc = (unsigned long long)((double)w * 4294967296.0);
    atomicAdd(&g_Drev[bN + norig], inc);

    float s = w;
    s += __shfl_xor_sync(FULLM, s, 8);
    s += __shfl_xor_sync(FULLM, s, 4);
    s += __shfl_xor_sync(FULLM, s, 2);
    s += __shfl_xor_sync(FULLM, s, 1);
    if (sub == 0) g_Dfwd[qglob] = 0.5f * s;
}

// Sparse Laplacian scatter.
__global__ void k_lap(float* __restrict__ out, int N, int total_edges)
{
    int e = blockIdx.x * blockDim.x + threadIdx.x;
    if (e >= total_edges) return;
    int q = e >> 4;
    int b = q / N;
    int i = q - b * N;
    int j = g_idx[e];
    float w = g_w[e];

    float Di = g_Dfwd[q]         + (float)((double)g_Drev[q]         * (0.5 / 4294967296.0));
    float Dj = g_Dfwd[b * N + j] + (float)((double)g_Drev[b * N + j] * (0.5 / 4294967296.0));
    float di = 1.0f / sqrtf(fmaxf(Di, 1e-6f));
    float dj = 1.0f / sqrtf(fmaxf(Dj, 1e-6f));
    float v = -((0.5f * w) * di) * dj;

    float* Lb = out + (size_t)b * N * (size_t)N;
    atomicAdd(Lb + (size_t)i * N + j, v);
    atomicAdd(Lb + (size_t)j * N + i, v);
}

extern "C" void kernel_launch(void* const* d_in, const int* in_sizes, int n_in,
                              void* d_out, int out_size)
{
    const float* xyz = (const float*)d_in[0];
    float* out = (float*)d_out;

    long long inel = in_sizes[0];                       // B*3*N
    int N = (int)((3LL * (long long)out_size) / inel);  // (3*B*N^2)/(3*B*N)
    int B = (int)(inel / (3LL * (long long)N));

    // 1) single-kernel prepass (hist + scan + reorder + Drev zero)
    k_bucket<<<B, 1024>>>(xyz, N, B);

    // 2) fused fill + KNN (round-8 structure)
    int nb_knn = B * (N / 64);        // 256 KNN blocks (64 queries each)
    int nb_ms  = 1792;                // grid-stride zero-fill blocks
    size_t smem = (size_t)N * sizeof(float4) + (size_t)N * sizeof(unsigned short)
                + (size_t)(NBUCK + 1) * sizeof(int);
    cudaFuncSetAttribute(k_knn_init, cudaFuncAttributeMaxDynamicSharedMemorySize, (int)smem);
    k_knn_init<<<nb_knn + nb_ms, TPB, smem>>>(out, N, B, nb_knn, nb_ms);

    // 3) Laplacian scatter
    int edges = B * N * KNN_K;
    int eb = (edges + 255) / 256;
    k_lap<<<eb, 256>>>(out, N, edges);
}

// round 11
// speedup vs baseline: 1.1991x; 1.0139x over previous
#include <cuda_runtime.h>
#include <math.h>
#include <float.h>

#define TPB    1024
#define KNN_K  16
#define NBUCK  64
#define FULLM  0xFFFFFFFFu
#define XMIN   (-4.8f)
#define XMAX   ( 4.8f)
#define BW     ((XMAX - XMIN) / (float)NBUCK)
#define INVBW  ((float)NBUCK / (XMAX - XMIN))
#define SAFE   1e-5f
#define FPRE   4          // rows each KNN block zero-fills before spinning

// scratch (static device arrays; allocation-free rule)
__device__ int                g_idx [65536 * KNN_K];
__device__ float              g_w   [65536 * KNN_K];
__device__ float              g_Dfwd[65536];
__device__ unsigned long long g_Drev[65536];

__device__ int            g_off [16 * (NBUCK + 1)];
__device__ float4         g_rc  [65536];             // reordered (x,y,z,|p|^2)
__device__ unsigned short g_rid [65536];             // orig index per position
__device__ int            g_ready;                   // bucket-done counter (0 at load; k_lap resets)

__device__ __forceinline__ int bucket_of_x(float x) {
    int ib = (int)((x - XMIN) * INVBW);
    return min(max(ib, 0), NBUCK - 1);
}

// zero one row + diagonal patch (lean streaming stores)
__device__ __forceinline__ void fill_row(float* __restrict__ out, int N, int r, int tid)
{
    const float4 z4 = make_float4(0.0f, 0.0f, 0.0f, 0.0f);
    int n4 = N >> 2;
    int b = r / N;
    int i = r - b * N;
    float4* row = reinterpret_cast<float4*>(out + ((size_t)b * N + i) * (size_t)N);
    #pragma unroll 2
    for (int f = tid; f < n4; f += TPB)
        __stcs(row + f, z4);
    int fd = i >> 2;
    if (tid == (fd & (TPB - 1))) {          // same thread re-writes same addr: ordered
        float4 v = z4;
        ((float*)&v)[i & 3] = 1.0f;
        __stcs(row + fd, v);
    }
}

// ---------- fused bucket + KNN + dense init ----------
// bids [0, B):              bucket prepass (hist+scan+reorder+Drev zero), flag arrive
// bids [B, B+nb_knn):       KNN (prefill FPRE rows, spin on flag, then knn)
// bids [B+nb_knn, ...):     zero-fill remaining rows (grid-stride)
__global__ void __launch_bounds__(TPB, 2)
k_fused(const float* __restrict__ xyz, float* __restrict__ out,
        int N, int B, int nb_knn, int nb_ms)
{
    extern __shared__ char smraw[];
    const int tid = threadIdx.x;
    const int bid = blockIdx.x;

    if (bid < B) {
        // ---------------- bucket prepass (one batch per block) ------------
        int* h   = reinterpret_cast<int*>(smraw);
        int* cur = h + NBUCK;
        const int b = bid;
        const int bN = b * N;
        const float* X = xyz + (size_t)b * 3 * N;

        if (tid < NBUCK) h[tid] = 0;
        __syncthreads();
        for (int n = tid; n < N; n += TPB) {
            g_Drev[bN + n] = 0ull;          // pre-zero for knn epilogue atomics
            atomicAdd(&h[bucket_of_x(X[n])], 1);
        }
        __syncthreads();
        if (tid < 32) {                     // warp 0: scan 64 counts
            int v0 = h[tid], v1 = h[tid + 32];
            int s0 = v0, s1 = v1;
            for (int d = 1; d < 32; d <<= 1) {
                int t0 = __shfl_up_sync(FULLM, s0, d);
                int t1 = __shfl_up_sync(FULLM, s1, d);
                if (tid >= d) { s0 += t0; s1 += t1; }
            }
            s1 += __shfl_sync(FULLM, s0, 31);
            int ob = b * (NBUCK + 1);
            if (tid == 0) g_off[ob] = 0;
            g_off[ob + 1 + tid]  = s0;
            g_off[ob + 33 + tid] = s1;
            cur[tid]      = s0 - v0;
            cur[tid + 32] = s1 - v1;
        }
        __syncthreads();
        for (int n = tid; n < N; n += TPB) {
            float x = X[n], y = X[N + n], z = X[2 * N + n];
            float sq = fmaf(x, x, fmaf(y, y, z * z));
            int pos = atomicAdd(&cur[bucket_of_x(x)], 1);
            g_rc [bN + pos] = make_float4(x, y, z, sq);
            g_rid[bN + pos] = (unsigned short)n;
        }
        __threadfence();
        __syncthreads();
        if (tid == 0) atomicAdd(&g_ready, 1);
        return;
    }

    if (bid >= B + nb_knn) {
        // ------------- zero-fill remaining rows (grid-stride) -------------
        int msid  = bid - B - nb_knn;
        int nrows = B * N;
        for (int r = nb_knn * FPRE + msid; r < nrows; r += nb_ms)
            fill_row(out, N, r, tid);
        return;
    }

    // ---------------- KNN role ----------------
    const int kb = bid - B;                     // 0 .. nb_knn-1

    // useful work while bucket prepass runs: prefill FPRE rows
    for (int r = kb * FPRE; r < kb * FPRE + FPRE; r++)
        fill_row(out, N, r, tid);

    // wait for bucket flag (bucket blocks have lower bids => wave-1 resident)
    if (tid == 0) {
        while (atomicAdd(&g_ready, 0) < B) __nanosleep(64);
    }
    __syncthreads();
    __threadfence();

    float4*         rc  = reinterpret_cast<float4*>(smraw);            // N float4
    unsigned short* rid = reinterpret_cast<unsigned short*>(rc + N);   // N ushort
    int*            off = reinterpret_cast<int*>(rid + N);             // NBUCK+1

    const int qpb = (TPB / 32) * 2;             // 64 queries per block
    const int blocks_per_b = N / qpb;
    const int b = kb / blocks_per_b;
    const int qbase = (kb - b * blocks_per_b) * qpb;
    const int bN = b * N;

    for (int n = tid; n < N; n += TPB) rc[n]  = g_rc[bN + n];
    for (int n = tid; n < N; n += TPB) rid[n] = g_rid[bN + n];
    if (tid <= NBUCK) off[tid] = g_off[b * (NBUCK + 1) + tid];
    __syncthreads();

    const int warp = tid >> 5, lane = tid & 31;
    const int g = lane >> 4, sub = lane & 15;
    const int pos0 = qbase + warp * 2;          // bucket-sorted positions

    // queries kept ONLY in pre-scaled form to save registers: a = -2q, qw=|q|^2
    float a0x, a0y, a0z, q0w, a1x, a1y, a1z, q1w;
    {
        float4 q0 = rc[pos0];
        float4 q1 = rc[pos0 + 1];
        a0x = -2.0f * q0.x; a0y = -2.0f * q0.y; a0z = -2.0f * q0.z; q0w = q0.w;
        a1x = -2.0f * q1.x; a1y = -2.0f * q1.y; a1z = -2.0f * q1.z; q1w = q1.w;
    }

    // sorted-across-lanes top-16 in e-space; li = POSITION in rc
    float ld = FLT_MAX; int li = 0;
    float wt0 = FLT_MAX, wt1 = FLT_MAX;

    auto process = [&](int start, int end) {
        for (int p = start; p < end; p += 32) {
            int pp = p + lane;
            bool valid = pp < end;
            float4 c = rc[valid ? pp : end - 1];
            float e0 = fmaf(a0x, c.x, fmaf(a0y, c.y, fmaf(a0z, c.z, c.w)));
            float e1 = fmaf(a1x, c.x, fmaf(a1y, c.y, fmaf(a1z, c.z, c.w)));
            unsigned bal0 = __ballot_sync(FULLM, valid && (e0 < wt0));
            unsigned bal1 = __ballot_sync(FULLM, valid && (e1 < wt1));
            if ((bal0 | bal1) == 0u) continue;
            do {
                int s0 = __ffs(bal0) - 1;
                int s1 = __ffs(bal1) - 1;
                float dd0 = __shfl_sync(FULLM, e0, s0 & 31);
                float dd1 = __shfl_sync(FULLM, e1, s1 & 31);
                bool have = g ? (bal1 != 0u) : (bal0 != 0u);
                float dd = g ? dd1 : dd0;
                int   jj = p + ((g ? s1 : s0) & 31);
                bool pr = have && (dd < ld);
                unsigned pb = __ballot_sync(FULLM, pr);
                float sld = __shfl_up_sync(FULLM, ld, 1);
                int   sli = __shfl_up_sync(FULLM, li, 1);
                bool prevpr = (sub > 0) && ((pb >> (lane - 1)) & 1u);
                if (pr) { ld = prevpr ? sld : dd; li = prevpr ? sli : jj; }
                bal0 &= bal0 - 1;
                bal1 &= bal1 - 1;
            } while (bal0 | bal1);
            wt0 = __shfl_sync(FULLM, ld, 15);
            wt1 = __shfl_sync(FULLM, ld, 31);
        }
    };

    // buckets of the two queries (binary search over off[], warp-uniform)
    int blo, bhi;
    {
        int lo = 0, hi = NBUCK - 1;
        while (lo < hi) { int mid = (lo + hi + 1) >> 1; if (off[mid] <= pos0) lo = mid; else hi = mid - 1; }
        blo = lo;
        lo = blo; hi = NBUCK - 1;
        int p1 = pos0 + 1;
        while (lo < hi) { int mid = (lo + hi + 1) >> 1; if (off[mid] <= p1) lo = mid; else hi = mid - 1; }
        bhi = lo;
    }

    process(off[blo], off[bhi + 1]);

    bool leftOpen = blo > 0, rightOpen = bhi < NBUCK - 1;
    while (leftOpen || rightOpen) {
        float qx0 = -0.5f * a0x, qx1 = -0.5f * a1x;
        float r20 = (wt0 + q0w) * 1.0001f + 1e-6f;    // d^2 bound, slack for fp
        float r21 = (wt1 + q1w) * 1.0001f + 1e-6f;
        float LBx = XMIN + blo * BW;
        float RBx = XMIN + (bhi + 1) * BW;
        if (leftOpen) {
            float gl0 = fmaxf(qx0 - LBx - SAFE, 0.0f);
            float gl1 = fmaxf(qx1 - LBx - SAFE, 0.0f);
            if (gl0 * gl0 >= r20 && gl1 * gl1 >= r21) leftOpen = false;
        }
        if (rightOpen) {
            float gr0 = fmaxf(RBx - qx0 - SAFE, 0.0f);
            float gr1 = fmaxf(RBx - qx1 - SAFE, 0.0f);
            if (gr0 * gr0 >= r20 && gr1 * gr1 >= r21) rightOpen = false;
        }
        if (!(leftOpen || rightOpen)) break;
        bool goLeft = (leftOpen && rightOpen) ? ((qx0 - LBx) < (RBx - qx1)) : leftOpen;
        if (goLeft) {
            blo--;
            process(off[blo], off[blo + 1]);
            leftOpen = blo > 0;
        } else {
            bhi++;
            process(off[bhi], off[bhi + 1]);
            rightOpen = bhi < NBUCK - 1;
        }
    }

    // epilogue: exact weight recomputation from coordinates (faithful to ref)
    float qx = -0.5f * (g ? a1x : a0x);
    float qy = -0.5f * (g ? a1y : a0y);
    float qz = -0.5f * (g ? a1z : a0z);
    const float4 nbp = rc[li];
    float dx = qx - nbp.x, dy = qy - nbp.y, dz = qz - nbp.z;
    float dist2 = fmaf(dx, dx, fmaf(dy, dy, dz * dz));
    float w = expf(-0.5f * dist2);

    const int qorig = rid[pos0 + g];
    const int qglob = bN + qorig;
    const int norig = rid[li];
    g_idx[qglob * KNN_K + sub] = norig;
    g_w [qglob * KNN_K + sub] = w;

    // reverse-degree scatter folded in (fixed-point => deterministic)
    unsigned long long inc = (unsigned long long)((double)w * 4294967296.0);
    atomicAdd(&g_Drev[bN + norig], inc);

    float s = w;
    s += __shfl_xor_sync(FULLM, s, 8);
    s += __shfl_xor_sync(FULLM, s, 4);
    s += __shfl_xor_sync(FULLM, s, 2);
    s += __shfl_xor_sync(FULLM, s, 1);
    if (sub == 0) g_Dfwd[qglob] = 0.5f * s;
}

// Sparse Laplacian scatter (+ flag reset for next graph replay).
__global__ void k_lap(float* __restrict__ out, int N, int total_edges)
{
    int e = blockIdx.x * blockDim.x + threadIdx.x;
    if (e == 0) g_ready = 0;                // stream-ordered: safe for next replay
    if (e >= total_edges) return;
    int q = e >> 4;
    int b = q / N;
    int i = q - b * N;
    int j = g_idx[e];
    float w = g_w[e];

    float Di = g_Dfwd[q]         + (float)((double)g_Drev[q]         * (0.5 / 4294967296.0));
    float Dj = g_Dfwd[b * N + j] + (float)((double)g_Drev[b * N + j] * (0.5 / 4294967296.0));
    float di = 1.0f / sqrtf(fmaxf(Di, 1e-6f));
    float dj = 1.0f / sqrtf(fmaxf(Dj, 1e-6f));
    float v = -((0.5f * w) * di) * dj;

    float* Lb = out + (size_t)b * N * (size_t)N;
    atomicAdd(Lb + (size_t)i * N + j, v);
    atomicAdd(Lb + (size_t)j * N + i, v);
}

extern "C" void kernel_launch(void* const* d_in, const int* in_sizes, int n_in,
                              void* d_out, int out_size)
{
    const float* xyz = (const float*)d_in[0];
    float* out = (float*)d_out;

    long long inel = in_sizes[0];                       // B*3*N
    int N = (int)((3LL * (long long)out_size) / inel);  // (3*B*N^2)/(3*B*N)
    int B = (int)(inel / (3LL * (long long)N));

    int nb_knn = B * (N / 64);        // 256 KNN blocks (64 queries each)
    int nb_ms  = 1792;                // grid-stride zero-fill blocks
    size_t smem = (size_t)N * sizeof(float4) + (size_t)N * sizeof(unsigned short)
                + (size_t)(NBUCK + 1) * sizeof(int);
    cudaFuncSetAttribute(k_fused, cudaFuncAttributeMaxDynamicSharedMemorySize, (int)smem);
    k_fused<<<B + nb_knn + nb_ms, TPB, smem>>>(xyz, out, N, B, nb_knn, nb_ms);

    int edges = B * N * KNN_K;
    int eb = (edges + 255) / 256;
    k_lap<<<eb, 256>>>(out, N, edges);
}

// round 12
// speedup vs baseline: 1.3680x; 1.1408x over previous
#include <cuda_runtime.h>
#include <math.h>
#include <float.h>

#define TPB    1024
#define KNN_K  16
#define NBUCK  64
#define FULLM  0xFFFFFFFFu
#define XMIN   (-4.8f)
#define XMAX   ( 4.8f)
#define BW     ((XMAX - XMIN) / (float)NBUCK)
#define INVBW  ((float)NBUCK / (XMAX - XMIN))
#define SAFE   1e-5f
#define FPRE   4          // rows each KNN block zero-fills before spinning

// scratch (static device arrays; allocation-free rule)
__device__ int                g_idx [65536 * KNN_K];
__device__ float              g_w   [65536 * KNN_K];
__device__ float              g_Dfwd[65536];
__device__ unsigned long long g_Drev[65536];

__device__ int            g_off [16 * (NBUCK + 1)];
__device__ float4         g_rc  [65536];             // reordered (x,y,z,|p|^2)
__device__ unsigned short g_rid [65536];             // orig index per position
__device__ int            g_ready;                   // bucket-done counter (0 at load; k_lap resets)

__device__ __forceinline__ int bucket_of_x(float x) {
    int ib = (int)((x - XMIN) * INVBW);
    return min(max(ib, 0), NBUCK - 1);
}

// zero one row + diagonal patch (lean streaming stores)
__device__ __forceinline__ void fill_row(float* __restrict__ out, int N, int r, int tid)
{
    const float4 z4 = make_float4(0.0f, 0.0f, 0.0f, 0.0f);
    int n4 = N >> 2;
    int b = r / N;
    int i = r - b * N;
    float4* row = reinterpret_cast<float4*>(out + ((size_t)b * N + i) * (size_t)N);
    #pragma unroll 2
    for (int f = tid; f < n4; f += TPB)
        __stcs(row + f, z4);
    int fd = i >> 2;
    if (tid == (fd & (TPB - 1))) {          // same thread re-writes same addr: ordered
        float4 v = z4;
        ((float*)&v)[i & 3] = 1.0f;
        __stcs(row + fd, v);
    }
}

// ---------- fused bucket + KNN + dense init ----------
// bids [0, B):              bucket prepass (hist+scan+reorder+Drev zero), flag arrive
// bids [B, B+nb_knn):       KNN (prefill FPRE rows, spin on flag, then knn)
// bids [B+nb_knn, ...):     zero-fill remaining rows (grid-stride)
__global__ void __launch_bounds__(TPB, 2)
k_fused(const float* __restrict__ xyz, float* __restrict__ out,
        int N, int B, int nb_knn, int nb_ms)
{
    extern __shared__ char smraw[];
    const int tid = threadIdx.x;
    const int bid = blockIdx.x;

    if (bid < B) {
        // ---------------- bucket prepass (one batch per block) ------------
        int* h   = reinterpret_cast<int*>(smraw);
        int* cur = h + NBUCK;
        const int b = bid;
        const int bN = b * N;
        const float* X = xyz + (size_t)b * 3 * N;

        if (tid < NBUCK) h[tid] = 0;
        __syncthreads();
        for (int n = tid; n < N; n += TPB) {
            g_Drev[bN + n] = 0ull;          // pre-zero for knn epilogue atomics
            atomicAdd(&h[bucket_of_x(X[n])], 1);
        }
        __syncthreads();
        if (tid < 32) {                     // warp 0: scan 64 counts
            int v0 = h[tid], v1 = h[tid + 32];
            int s0 = v0, s1 = v1;
            for (int d = 1; d < 32; d <<= 1) {
                int t0 = __shfl_up_sync(FULLM, s0, d);
                int t1 = __shfl_up_sync(FULLM, s1, d);
                if (tid >= d) { s0 += t0; s1 += t1; }
            }
            s1 += __shfl_sync(FULLM, s0, 31);
            int ob = b * (NBUCK + 1);
            if (tid == 0) g_off[ob] = 0;
            g_off[ob + 1 + tid]  = s0;
            g_off[ob + 33 + tid] = s1;
            cur[tid]      = s0 - v0;
            cur[tid + 32] = s1 - v1;
        }
        __syncthreads();
        for (int n = tid; n < N; n += TPB) {
            float x = X[n], y = X[N + n], z = X[2 * N + n];
            float sq = fmaf(x, x, fmaf(y, y, z * z));
            int pos = atomicAdd(&cur[bucket_of_x(x)], 1);
            g_rc [bN + pos] = make_float4(x, y, z, sq);
            g_rid[bN + pos] = (unsigned short)n;
        }
        __threadfence();
        __syncthreads();
        if (tid == 0) atomicAdd(&g_ready, 1);
        return;
    }

    if (bid >= B + nb_knn) {
        // ------------- zero-fill remaining rows (grid-stride) -------------
        int msid  = bid - B - nb_knn;
        int nrows = B * N;
        for (int r = nb_knn * FPRE + msid; r < nrows; r += nb_ms)
            fill_row(out, N, r, tid);
        return;
    }

    // ---------------- KNN role ----------------
    const int kb = bid - B;                     // 0 .. nb_knn-1

    // useful work while bucket prepass runs: prefill FPRE rows
    for (int r = kb * FPRE; r < kb * FPRE + FPRE; r++)
        fill_row(out, N, r, tid);

    // wait for bucket flag (bucket blocks have lower bids => wave-1 resident)
    if (tid == 0) {
        while (atomicAdd(&g_ready, 0) < B) __nanosleep(64);
    }
    __syncthreads();
    __threadfence();

    float4*         rc  = reinterpret_cast<float4*>(smraw);            // N float4
    unsigned short* rid = reinterpret_cast<unsigned short*>(rc + N);   // N ushort
    int*            off = reinterpret_cast<int*>(rid + N);             // NBUCK+1

    const int qpb = (TPB / 32) * 2;             // 64 queries per block
    const int blocks_per_b = N / qpb;
    const int b = kb / blocks_per_b;
    const int qbase = (kb - b * blocks_per_b) * qpb;
    const int bN = b * N;

    for (int n = tid; n < N; n += TPB) rc[n]  = g_rc[bN + n];
    for (int n = tid; n < N; n += TPB) rid[n] = g_rid[bN + n];
    if (tid <= NBUCK) off[tid] = g_off[b * (NBUCK + 1) + tid];
    __syncthreads();

    const int warp = tid >> 5, lane = tid & 31;
    const int g = lane >> 4, sub = lane & 15;
    const int pos0 = qbase + warp * 2;          // bucket-sorted positions

    // queries kept ONLY in pre-scaled form to save registers: a = -2q, qw=|q|^2
    float a0x, a0y, a0z, q0w, a1x, a1y, a1z, q1w;
    {
        float4 q0 = rc[pos0];
        float4 q1 = rc[pos0 + 1];
        a0x = -2.0f * q0.x; a0y = -2.0f * q0.y; a0z = -2.0f * q0.z; q0w = q0.w;
        a1x = -2.0f * q1.x; a1y = -2.0f * q1.y; a1z = -2.0f * q1.z; q1w = q1.w;
    }

    // density-seeded screening thresholds in e-space (~40 expected pts in ball)
    const float seed0 = 0.1107f * __expf(q0w * (1.0f / 3.0f)) - q0w;
    const float seed1 = 0.1107f * __expf(q1w * (1.0f / 3.0f)) - q1w;

    // sorted-across-lanes top-16 in e-space; li = POSITION in rc
    float ld = FLT_MAX; int li = 0;
    float wt0, wt1;

    auto process = [&](int start, int end) {
        for (int p = start; p < end; p += 32) {
            int pp = p + lane;
            bool valid = pp < end;
            float4 c = rc[valid ? pp : end - 1];
            float e0 = fmaf(a0x, c.x, fmaf(a0y, c.y, fmaf(a0z, c.z, c.w)));
            float e1 = fmaf(a1x, c.x, fmaf(a1y, c.y, fmaf(a1z, c.z, c.w)));
            unsigned bal0 = __ballot_sync(FULLM, valid && (e0 < wt0));
            unsigned bal1 = __ballot_sync(FULLM, valid && (e1 < wt1));
            if ((bal0 | bal1) == 0u) continue;
            do {
                int s0 = __ffs(bal0) - 1;
                int s1 = __ffs(bal1) - 1;
                float dd0 = __shfl_sync(FULLM, e0, s0 & 31);
                float dd1 = __shfl_sync(FULLM, e1, s1 & 31);
                bool have = g ? (bal1 != 0u) : (bal0 != 0u);
                float dd = g ? dd1 : dd0;
                int   jj = p + ((g ? s1 : s0) & 31);
                bool pr = have && (dd < ld);
                unsigned pb = __ballot_sync(FULLM, pr);
                float sld = __shfl_up_sync(FULLM, ld, 1);
                int   sli = __shfl_up_sync(FULLM, li, 1);
                bool prevpr = (sub > 0) && ((pb >> (lane - 1)) & 1u);
                if (pr) { ld = prevpr ? sld : dd; li = prevpr ? sli : jj; }
                bal0 &= bal0 - 1;
                bal1 &= bal1 - 1;
            } while (bal0 | bal1);
            // monotone non-increasing thresholds (min with seed when underfull)
            wt0 = fminf(wt0, __shfl_sync(FULLM, ld, 15));
            wt1 = fminf(wt1, __shfl_sync(FULLM, ld, 31));
        }
    };

    // home buckets of the two queries (binary search over off[], warp-uniform)
    int hlo, hhi;
    {
        int lo = 0, hi = NBUCK - 1;
        while (lo < hi) { int mid = (lo + hi + 1) >> 1; if (off[mid] <= pos0) lo = mid; else hi = mid - 1; }
        hlo = lo;
        lo = hlo; hi = NBUCK - 1;
        int p1 = pos0 + 1;
        while (lo < hi) { int mid = (lo + hi + 1) >> 1; if (off[mid] <= p1) lo = mid; else hi = mid - 1; }
        hhi = lo;
    }

    for (int attempt = 0; attempt < 2; attempt++) {
        ld = FLT_MAX; li = 0;
        wt0 = attempt ? FLT_MAX : seed0;
        wt1 = attempt ? FLT_MAX : seed1;
        int blo = hlo, bhi = hhi;

        process(off[blo], off[bhi + 1]);

        bool leftOpen = blo > 0, rightOpen = bhi < NBUCK - 1;
        while (leftOpen || rightOpen) {
            float qx0 = -0.5f * a0x, qx1 = -0.5f * a1x;
            float r20 = (wt0 + q0w) * 1.0001f + 1e-6f;  // d^2 bound, fp slack
            float r21 = (wt1 + q1w) * 1.0001f + 1e-6f;
            float LBx = XMIN + blo * BW;
            float RBx = XMIN + (bhi + 1) * BW;
            if (leftOpen) {
                float gl0 = fmaxf(qx0 - LBx - SAFE, 0.0f);
                float gl1 = fmaxf(qx1 - LBx - SAFE, 0.0f);
                if (gl0 * gl0 >= r20 && gl1 * gl1 >= r21) leftOpen = false;
            }
            if (rightOpen) {
                float gr0 = fmaxf(RBx - qx0 - SAFE, 0.0f);
                float gr1 = fmaxf(RBx - qx1 - SAFE, 0.0f);
                if (gr0 * gr0 >= r20 && gr1 * gr1 >= r21) rightOpen = false;
            }
            if (!(leftOpen || rightOpen)) break;
            bool goLeft = (leftOpen && rightOpen) ? ((qx0 - LBx) < (RBx - qx1)) : leftOpen;
            if (goLeft) {
                blo--;
                process(off[blo], off[blo + 1]);
                leftOpen = blo > 0;
            } else {
                bhi++;
                process(off[bhi], off[bhi + 1]);
                rightOpen = bhi < NBUCK - 1;
            }
        }

        float l15 = __shfl_sync(FULLM, ld, 15);
        float l31 = __shfl_sync(FULLM, ld, 31);
        if (l15 != FLT_MAX && l31 != FLT_MAX) break;   // both lists full => exact
    }

    // epilogue: exact weight recomputation from coordinates (faithful to ref)
    float qx = -0.5f * (g ? a1x : a0x);
    float qy = -0.5f * (g ? a1y : a0y);
    float qz = -0.5f * (g ? a1z : a0z);
    const float4 nbp = rc[li];
    float dx = qx - nbp.x, dy = qy - nbp.y, dz = qz - nbp.z;
    float dist2 = fmaf(dx, dx, fmaf(dy, dy, dz * dz));
    float w = expf(-0.5f * dist2);

    const int qorig = rid[pos0 + g];
    const int qglob = bN + qorig;
    const int norig = rid[li];
    g_idx[qglob * KNN_K + sub] = norig;
    g_w [qglob * KNN_K + sub] = w;

    // reverse-degree scatter folded in (fixed-point => deterministic)
    unsigned long long inc = (unsigned long long)((double)w * 4294967296.0);
    atomicAdd(&g_Drev[bN + norig], inc);

    float s = w;
    s += __shfl_xor_sync(FULLM, s, 8);
    s += __shfl_xor_sync(FULLM, s, 4);
    s += __shfl_xor_sync(FULLM, s, 2);
    s += __shfl_xor_sync(FULLM, s, 1);
    if (sub == 0) g_Dfwd[qglob] = 0.5f * s;
}

// Sparse Laplacian scatter (+ flag reset for next graph replay).
__global__ void k_lap(float* __restrict__ out, int N, int total_edges)
{
    int e = blockIdx.x * blockDim.x + threadIdx.x;
    if (e == 0) g_ready = 0;                // stream-ordered: safe for next replay
    if (e >= total_edges) return;
    int q = e >> 4;
    int b = q / N;
    int i = q - b * N;
    int j = g_idx[e];
    float w = g_w[e];

    float Di = g_Dfwd[q]         + (float)((double)g_Drev[q]         * (0.5 / 4294967296.0));
    float Dj = g_Dfwd[b * N + j] + (float)((double)g_Drev[b * N + j] * (0.5 / 4294967296.0));
    float di = 1.0f / sqrtf(fmaxf(Di, 1e-6f));
    float dj = 1.0f / sqrtf(fmaxf(Dj, 1e-6f));
    float v = -((0.5f * w) * di) * dj;

    float* Lb = out + (size_t)b * N * (size_t)N;
    atomicAdd(Lb + (size_t)i * N + j, v);
    atomicAdd(Lb + (size_t)j * N + i, v);
}

extern "C" void kernel_launch(void* const* d_in, const int* in_sizes, int n_in,
                              void* d_out, int out_size)
{
    const float* xyz = (const float*)d_in[0];
    float* out = (float*)d_out;

    long long inel = in_sizes[0];                       // B*3*N
    int N = (int)((3LL * (long long)out_size) / inel);  // (3*B*N^2)/(3*B*N)
    int B = (int)(inel / (3LL * (long long)N));

    int nb_knn = B * (N / 64);        // 256 KNN blocks (64 queries each)
    int nb_ms  = 1792;                // grid-stride zero-fill blocks
    size_t smem = (size_t)N * sizeof(float4) + (size_t)N * sizeof(unsigned short)
                + (size_t)(NBUCK + 1) * sizeof(int);
    cudaFuncSetAttribute(k_fused, cudaFuncAttributeMaxDynamicSharedMemorySize, (int)smem);
    k_fused<<<B + nb_knn + nb_ms, TPB, smem>>>(xyz, out, N, B, nb_knn, nb_ms);

    int edges = B * N * KNN_K;
    int eb = (edges + 255) / 256;
    k_lap<<<eb, 256>>>(out, N, edges);
}